// round 17
// baseline (speedup 1.0000x reference)
#include <cuda_runtime.h>
#include <math.h>
#include <stdint.h>

#define BB 2
#define LL 2048
#define DD 256
#define PP 32
#define NTOK (BB*LL)
#define NCH 16
#define CH 128
#define NBLK 128
#define NTHR 512

// ---------------- scratch ----------------
__device__ float d_cq[NTOK*PP];
__device__ float d_sq[NTOK*PP];
__device__ float d_g [NTOK];
__device__ float d_gc[NTOK];
__device__ float d_v [NTOK*DD];
__device__ float d_ret[NTOK*DD];
__device__ float d_t1[NTOK*2*DD];
__device__ float d_t2[NTOK*DD];
__device__ float d_state[BB*64*64*DD];
__device__ float d_pref [BB*NCH*64*DD];
__device__ float d_gpart[NTOK*8];
__device__ float d_s1 [8*NTOK];
__device__ float d_s2 [8*NTOK];
__device__ float d_s1b[8*NTOK];
__device__ float d_s2b[8*NTOK];

// flag-array grid barrier (no atomics; generations persist across graph replays)
__device__ volatile unsigned d_flag[NBLK];
__device__ volatile unsigned d_gen;

__device__ __forceinline__ void gbar(unsigned* sb){
    __syncthreads();
    __threadfence();
    const unsigned target = sb[0] + sb[1] + 1u;
    const int blk = blockIdx.x, tid = threadIdx.x;
    if (blk == 0){
        if (tid > 0 && tid < NBLK){
            while (d_flag[tid] < target) { }
        }
        __syncthreads();
        if (tid == 0){
            __threadfence();
            d_gen = target;
        }
    } else {
        if (tid == 0){
            d_flag[blk] = target;
            while (d_gen < target) { __nanosleep(32); }
            __threadfence();
        }
    }
    __syncthreads();
    if (tid == 0) sb[1]++;
    __syncthreads();
}

__device__ __forceinline__ float gelu_f(float x){
    return 0.5f*x*(1.0f+erff(x*0.7071067811865476f));
}
__device__ __forceinline__ float phasor(int b, int tok, int c){
    int t = b*LL + tok;
    return (c < 32) ? d_cq[t*PP + c] : d_sq[t*PP + c - 32];
}
__device__ __forceinline__ uint32_t f2tf(float f){
    uint32_t r; asm("cvt.rna.tf32.f32 %0, %1;" : "=r"(r) : "f"(f)); return r;
}
__device__ __forceinline__ uint32_t fb(float f){ return __float_as_uint(f); }
__device__ __forceinline__ float f2tf_as_f(float f){
    uint32_t r = f2tf(f); return __uint_as_float(r);
}
__device__ __forceinline__ void mma_tf32(float* c, const uint32_t* a, const uint32_t* b){
    asm volatile(
      "mma.sync.aligned.m16n8k8.row.col.f32.tf32.tf32.f32 "
      "{%0,%1,%2,%3}, {%4,%5,%6,%7}, {%8,%9}, {%0,%1,%2,%3};\n"
      : "+f"(c[0]), "+f"(c[1]), "+f"(c[2]), "+f"(c[3])
      : "r"(a[0]), "r"(a[1]), "r"(a[2]), "r"(a[3]), "r"(b[0]), "r"(b[1]));
}
__device__ __forceinline__ void ldsm4(uint32_t* r, uint32_t addr){
    asm volatile("ldmatrix.sync.aligned.m8n8.x4.shared.b16 {%0,%1,%2,%3}, [%4];\n"
        : "=r"(r[0]), "=r"(r[1]), "=r"(r[2]), "=r"(r[3]) : "r"(addr));
}
__device__ __forceinline__ uint32_t shaddr(const void* p){
    return (uint32_t)__cvta_generic_to_shared(p);
}
__device__ __forceinline__ uint32_t ldsm_off(int lane, int row0, int P){
    int t8 = lane >> 3, r8 = lane & 7;
    return (uint32_t)(((row0 + r8 + (t8 & 1)*8)*P + (t8 >> 1)*4) * 4);
}

__device__ __forceinline__ void cp16(uint32_t dst, const void* src, int sz){
    asm volatile("cp.async.cg.shared.global [%0], [%1], 16, %2;\n"
                 :: "r"(dst), "l"(src), "r"(sz));
}
__device__ __forceinline__ void cp_commit(){ asm volatile("cp.async.commit_group;\n"); }
__device__ __forceinline__ void cp_wait1(){ asm volatile("cp.async.wait_group 1;\n"); }

#define A_PLAIN  0
#define A_CONCAT 1
#define A_LN     2
#define E_NONE 0
#define E_GELU 1
#define E_OUT  3
#define E_GATE 4
#define E_STAT 5

#define APITCH 36
#define WPITCH 72

// ---------------- generic GEMM tile (phases G, H) ----------------
template<int AMODE, int EPI>
__device__ void gemm_tile(float* smem,
                 const float* __restrict__ A,
                 const float* __restrict__ W,
                 const float* __restrict__ bias,
                 float* __restrict__ C,
                 const float* __restrict__ extra,
                 const float* __restrict__ lnS1, const float* __restrict__ lnS2,
                 const float* __restrict__ lnG,  const float* __restrict__ lnB,
                 float* __restrict__ oS1, float* __restrict__ oS2,
                 int m0, int n0, int M, int N, int K)
{
    float* Asm = smem;
    float* Wsm = smem + 3*128*APITCH;

    const int tid = threadIdx.x;
    const int wid = tid >> 5;
    const int lane = tid & 31;
    const int grp = lane >> 2;
    const int tig = lane & 3;
    const int wm = wid >> 1;
    const int wn = wid & 1;

    float acc[4][4];
    #pragma unroll
    for (int nt=0;nt<4;nt++)
        #pragma unroll
        for (int i=0;i<4;i++) acc[nt][i]=0.f;

    float4 areg[2]; float4 gv4, bv4;
    float mrow[2], rsrow[2];
    if (AMODE == A_LN){
        #pragma unroll
        for (int it=0; it<2; it++){
            int r = m0 + (tid>>3) + it*64;
            float sa = 0.f, sb = 0.f;
            #pragma unroll
            for (int s=0; s<8; s++){ sa += lnS1[s*NTOK + r]; sb += lnS2[s*NTOK + r]; }
            float mean = sa*(1.f/256.f);
            float var = fmaxf(sb*(1.f/256.f) - mean*mean, 0.f);
            mrow[it] = mean;
            rsrow[it] = rsqrtf(var + 1e-5f);
        }
    }

    auto ldA_regs = [&](int k0){
        int kq = (tid & 7)*4;
        gv4 = *(const float4*)&lnG[k0+kq];
        bv4 = *(const float4*)&lnB[k0+kq];
        #pragma unroll
        for (int it=0; it<2; it++){
            int r = m0 + (tid>>3) + it*64;
            areg[it] = *(const float4*)&A[(size_t)r*K + k0 + kq];
        }
    };
    auto stA = [&](int buf){
        float* As = Asm + buf*128*APITCH;
        int kq = (tid & 7)*4;
        #pragma unroll
        for (int it=0; it<2; it++){
            int row = (tid>>3) + it*64;
            float4 v = areg[it];
            v.x = (v.x - mrow[it])*rsrow[it]*gv4.x + bv4.x;
            v.y = (v.y - mrow[it])*rsrow[it]*gv4.y + bv4.y;
            v.z = (v.z - mrow[it])*rsrow[it]*gv4.z + bv4.z;
            v.w = (v.w - mrow[it])*rsrow[it]*gv4.w + bv4.w;
            *(float4*)&As[row*APITCH + kq] = v;
        }
    };

    auto load_tiles = [&](int buf, int k0){
        float* As = Asm + buf*128*APITCH;
        float* Ws = Wsm + buf*32*WPITCH;
        if (AMODE != A_LN){
            #pragma unroll
            for (int it = 0; it < 2; it++){
                int linear = tid + it*NTHR;
                int row = linear >> 3;
                int kq  = (linear & 7)*4;
                int m = m0 + row;
                int kg = k0 + kq;
                const float* src = A + (size_t)m*K + kg;
                cp16((uint32_t)__cvta_generic_to_shared(&As[row*APITCH + kq]), src, 16);
            }
        }
        {
            int row = tid >> 4;
            int wnq = (tid & 15)*4;
            const float* src = W + (size_t)(k0+row)*N + n0 + wnq;
            cp16((uint32_t)__cvta_generic_to_shared(&Ws[row*WPITCH + wnq]), src, 16);
        }
    };

    const uint32_t aoff = ldsm_off(lane, wm*16, APITCH);

    const int ntiles = K >> 5;
    if (AMODE == A_LN) ldA_regs(0);
    load_tiles(0, 0);
    cp_commit();
    if (AMODE == A_LN) stA(0);
    if (AMODE == A_LN) ldA_regs(32);
    load_tiles(1, 32);
    cp_commit();
    if (AMODE == A_LN) stA(1);

    for (int kt = 0; kt < ntiles; kt++){
        int buf = kt % 3;
        cp_wait1();
        __syncthreads();

        if (kt+2 < ntiles){
            if (AMODE == A_LN) ldA_regs((kt+2)*32);
            load_tiles((kt+2)%3, (kt+2)*32);
        }
        cp_commit();

        const float* Ws = Wsm + buf*32*WPITCH;
        const uint32_t abase = shaddr(Asm + buf*128*APITCH) + aoff;
        #pragma unroll
        for (int ks = 0; ks < 32; ks += 8){
            uint32_t afr[4], bfr[4][2];
            ldsm4(afr, abase + ks*4);
            #pragma unroll
            for (int nt=0; nt<4; nt++){
                int cb = wn*32 + nt*8 + grp;
                bfr[nt][0] = fb(Ws[(ks + tig    )*WPITCH + cb]);
                bfr[nt][1] = fb(Ws[(ks + tig + 4)*WPITCH + cb]);
            }
            #pragma unroll
            for (int nt=0; nt<4; nt++)
                mma_tf32(acc[nt], afr, bfr[nt]);
        }
        if (AMODE == A_LN && kt+2 < ntiles) stA((kt+2)%3);
    }

    #pragma unroll
    for (int half=0; half<2; half++){
        int r = m0 + wm*16 + grp + half*8;
        float s = 0.f, ss = 0.f;
        #pragma unroll
        for (int nt=0; nt<4; nt++){
            int cb = n0 + wn*32 + nt*8 + 2*tig;
            float v0 = acc[nt][half*2+0] + bias[cb];
            float v1 = acc[nt][half*2+1] + bias[cb+1];
            if (EPI == E_GELU){ v0 = gelu_f(v0); v1 = gelu_f(v1); }
            if (EPI == E_OUT) { v0 += extra[(size_t)r*DD + cb];
                                v1 += extra[(size_t)r*DD + cb + 1]; }
            if (EPI == E_STAT){ s += v0 + v1; ss += v0*v0 + v1*v1; }
            *(float2*)&C[(size_t)r*N + cb] = make_float2(v0, v1);
        }
        if (EPI == E_STAT){
            s  += __shfl_xor_sync(0xffffffffu, s, 1);
            s  += __shfl_xor_sync(0xffffffffu, s, 2);
            ss += __shfl_xor_sync(0xffffffffu, ss, 1);
            ss += __shfl_xor_sync(0xffffffffu, ss, 2);
            if (tig == 0){
                int slot = (n0 >> 6)*2 + wn;
                oS1[slot*NTOK + r] = s;
                oS2[slot*NTOK + r] = ss;
            }
        }
    }
}

// ---------------- phase-A fused GEMM: gate + Wv sharing A ----------------
__device__ void gemm_tile_a(float* smem,
                 const float* __restrict__ x,
                 const float* __restrict__ Wg1, const float* __restrict__ bg1,
                 const float* __restrict__ gw,  float* __restrict__ gpart,
                 const float* __restrict__ Wv,  const float* __restrict__ bv,
                 float* __restrict__ Cv,
                 int m0, int n0)
{
    const int KG = 2*DD;
    float* Asm = smem;
    float* Wsm = smem + 3*128*APITCH;

    const int tid = threadIdx.x;
    const int wid = tid >> 5;
    const int lane = tid & 31;
    const int grp = lane >> 2;
    const int tig = lane & 3;
    const int wm = wid >> 1;
    const int wn = wid & 1;

    float accg[4][4], accv[4][4];
    #pragma unroll
    for (int nt=0;nt<4;nt++)
        #pragma unroll
        for (int i=0;i<4;i++){ accg[nt][i]=0.f; accv[nt][i]=0.f; }

    auto load_tiles = [&](int buf, int k0){
        float* As = Asm + buf*128*APITCH;
        float* Ws = Wsm + buf*2*32*WPITCH;
        #pragma unroll
        for (int it = 0; it < 2; it++){
            int linear = tid + it*NTHR;
            int row = linear >> 3;
            int kq  = (linear & 7)*4;
            int m = m0 + row;
            int kg = k0 + kq;
            const float* src; int sz = 16;
            if (kg < DD) src = x + (size_t)m*DD + kg;
            else {
                int l = m & (LL-1);
                if (l == 0){ sz = 0; src = x; }
                else src = x + (size_t)(m-1)*DD + (kg-DD);
            }
            cp16((uint32_t)__cvta_generic_to_shared(&As[row*APITCH + kq]), src, sz);
        }
        {
            int row = tid >> 4;
            int wnq = (tid & 15)*4;
            const float* src = Wg1 + (size_t)(k0+row)*DD + n0 + wnq;
            cp16((uint32_t)__cvta_generic_to_shared(&Ws[row*WPITCH + wnq]), src, 16);
            if (k0 < DD){
                const float* srcv = Wv + (size_t)(k0+row)*DD + n0 + wnq;
                cp16((uint32_t)__cvta_generic_to_shared(&Ws[32*WPITCH + row*WPITCH + wnq]), srcv, 16);
            }
        }
    };

    const uint32_t aoff = ldsm_off(lane, wm*16, APITCH);
    const int ntiles = KG >> 5;
    load_tiles(0, 0);  cp_commit();
    load_tiles(1, 32); cp_commit();

    for (int kt = 0; kt < ntiles; kt++){
        int buf = kt % 3;
        cp_wait1();
        __syncthreads();
        if (kt+2 < ntiles) load_tiles((kt+2)%3, (kt+2)*32);
        cp_commit();

        const float* Ws = Wsm + buf*2*32*WPITCH;
        const uint32_t abase = shaddr(Asm + buf*128*APITCH) + aoff;
        const bool dov = (kt < 8);
        #pragma unroll
        for (int ks = 0; ks < 32; ks += 8){
            uint32_t afr[4];
            ldsm4(afr, abase + ks*4);
            #pragma unroll
            for (int nt=0; nt<4; nt++){
                uint32_t bfr[2];
                int cb = wn*32 + nt*8 + grp;
                bfr[0] = fb(Ws[(ks + tig    )*WPITCH + cb]);
                bfr[1] = fb(Ws[(ks + tig + 4)*WPITCH + cb]);
                mma_tf32(accg[nt], afr, bfr);
            }
            if (dov){
                const float* Wh = Ws + 32*WPITCH;
                #pragma unroll
                for (int nt=0; nt<4; nt++){
                    uint32_t bfr[2];
                    int cb = wn*32 + nt*8 + grp;
                    bfr[0] = fb(Wh[(ks + tig    )*WPITCH + cb]);
                    bfr[1] = fb(Wh[(ks + tig + 4)*WPITCH + cb]);
                    mma_tf32(accv[nt], afr, bfr);
                }
            }
        }
    }

    int slot = (n0 >> 6)*2 + wn;
    #pragma unroll
    for (int half=0; half<2; half++){
        int r = m0 + wm*16 + grp + half*8;
        float part = 0.f;
        #pragma unroll
        for (int nt=0; nt<4; nt++){
            int cb = n0 + wn*32 + nt*8 + 2*tig;
            float v0 = gelu_f(accg[nt][half*2+0] + bg1[cb]);
            float v1 = gelu_f(accg[nt][half*2+1] + bg1[cb+1]);
            part += v0*gw[cb] + v1*gw[cb+1];
        }
        part += __shfl_xor_sync(0xffffffffu, part, 1);
        part += __shfl_xor_sync(0xffffffffu, part, 2);
        if (tig == 0)
            gpart[(size_t)r*8 + slot] = part;
    }
    #pragma unroll
    for (int half=0; half<2; half++){
        int r = m0 + wm*16 + grp + half*8;
        #pragma unroll
        for (int nt=0; nt<4; nt++){
            int cb = n0 + wn*32 + nt*8 + 2*tig;
            float v0 = accv[nt][half*2+0] + bv[cb];
            float v1 = accv[nt][half*2+1] + bv[cb+1];
            *(float2*)&Cv[(size_t)r*DD + cb] = make_float2(v0, v1);
        }
    }
}

// ---------------- dual-N GEMM for phase F ----------------
__device__ void gemm_tile_f(float* smem,
                 const float* __restrict__ A,
                 const float* __restrict__ W,
                 const float* __restrict__ bias,
                 float* __restrict__ C,
                 const float* __restrict__ lnS1, const float* __restrict__ lnS2,
                 const float* __restrict__ lnG,  const float* __restrict__ lnB,
                 int m0, int n0)
{
    const int N = 2*DD, K = DD;
    float* Asm = smem;
    float* Wsm = smem + 3*128*APITCH;

    const int tid = threadIdx.x;
    const int wid = tid >> 5;
    const int lane = tid & 31;
    const int grp = lane >> 2;
    const int tig = lane & 3;
    const int wm = wid >> 1;
    const int wn = wid & 1;

    float acc[2][4][4];
    #pragma unroll
    for (int h=0;h<2;h++)
        #pragma unroll
        for (int nt=0;nt<4;nt++)
            #pragma unroll
            for (int i=0;i<4;i++) acc[h][nt][i]=0.f;

    float4 areg[2]; float4 gv4, bv4;
    float mrow[2], rsrow[2];
    #pragma unroll
    for (int it=0; it<2; it++){
        int r = m0 + (tid>>3) + it*64;
        float sa = 0.f, sb = 0.f;
        #pragma unroll
        for (int s=0; s<8; s++){ sa += lnS1[s*NTOK + r]; sb += lnS2[s*NTOK + r]; }
        float mean = sa*(1.f/256.f);
        float var = fmaxf(sb*(1.f/256.f) - mean*mean, 0.f);
        mrow[it] = mean;
        rsrow[it] = rsqrtf(var + 1e-5f);
    }

    auto ldA_regs = [&](int k0){
        int kq = (tid & 7)*4;
        gv4 = *(const float4*)&lnG[k0+kq];
        bv4 = *(const float4*)&lnB[k0+kq];
        #pragma unroll
        for (int it=0; it<2; it++){
            int r = m0 + (tid>>3) + it*64;
            areg[it] = *(const float4*)&A[(size_t)r*K + k0 + kq];
        }
    };
    auto stA = [&](int buf){
        float* As = Asm + buf*128*APITCH;
        int kq = (tid & 7)*4;
        #pragma unroll
        for (int it=0; it<2; it++){
            int row = (tid>>3) + it*64;
            float4 v = areg[it];
            v.x = (v.x - mrow[it])*rsrow[it]*gv4.x + bv4.x;
            v.y = (v.y - mrow[it])*rsrow[it]*gv4.y + bv4.y;
            v.z = (v.z - mrow[it])*rsrow[it]*gv4.z + bv4.z;
            v.w = (v.w - mrow[it])*rsrow[it]*gv4.w + bv4.w;
            *(float4*)&As[row*APITCH + kq] = v;
        }
    };
    auto load_W = [&](int buf, int k0){
        float* Ws = Wsm + buf*2*32*WPITCH;
        int row = tid >> 4;
        int wnq = (tid & 15)*4;
        #pragma unroll
        for (int h = 0; h < 2; h++){
            const float* src = W + (size_t)(k0+row)*N + n0 + h*256 + wnq;
            cp16((uint32_t)__cvta_generic_to_shared(&Ws[h*32*WPITCH + row*WPITCH + wnq]), src, 16);
        }
    };

    const uint32_t aoff = ldsm_off(lane, wm*16, APITCH);
    const int ntiles = K >> 5;
    ldA_regs(0); load_W(0, 0); cp_commit(); stA(0);
    ldA_regs(32); load_W(1, 32); cp_commit(); stA(1);

    for (int kt = 0; kt < ntiles; kt++){
        int buf = kt % 3;
        cp_wait1();
        __syncthreads();
        if (kt+2 < ntiles){ ldA_regs((kt+2)*32); load_W((kt+2)%3, (kt+2)*32); }
        cp_commit();

        const float* Ws = Wsm + buf*2*32*WPITCH;
        const uint32_t abase = shaddr(Asm + buf*128*APITCH) + aoff;
        #pragma unroll
        for (int ks = 0; ks < 32; ks += 8){
            uint32_t afr[4];
            ldsm4(afr, abase + ks*4);
            #pragma unroll
            for (int h=0; h<2; h++){
                const float* Wh = Ws + h*32*WPITCH;
                #pragma unroll
                for (int nt=0; nt<4; nt++){
                    uint32_t bfr[2];
                    int cb = wn*32 + nt*8 + grp;
                    bfr[0] = fb(Wh[(ks + tig    )*WPITCH + cb]);
                    bfr[1] = fb(Wh[(ks + tig + 4)*WPITCH + cb]);
                    mma_tf32(acc[h][nt], afr, bfr);
                }
            }
        }
        if (kt+2 < ntiles) stA((kt+2)%3);
    }

    #pragma unroll
    for (int h=0; h<2; h++){
        #pragma unroll
        for (int half=0; half<2; half++){
            int r = m0 + wm*16 + grp + half*8;
            #pragma unroll
            for (int nt=0; nt<4; nt++){
                int cb = n0 + h*256 + wn*32 + nt*8 + 2*tig;
                float v0 = gelu_f(acc[h][nt][half*2+0] + bias[cb]);
                float v1 = gelu_f(acc[h][nt][half*2+1] + bias[cb+1]);
                *(float2*)&C[(size_t)r*N + cb] = make_float2(v0, v1);
            }
        }
    }
}

// ---------------- phases job: smem-staged ----------------
__device__ void phases_job(int blk, const float* __restrict__ x,
                           const float* __restrict__ Wk,
                           const float* __restrict__ bk,
                           float* smem){
    __syncthreads();
    float* xs = smem;
    float* wk = smem + 32*256;
    const int tid = threadIdx.x;
    const int rowbase = blk*32;
    for (int i = tid; i < 32*64; i += NTHR){
        int r = i >> 6, c4 = (i & 63)*4;
        *(float4*)&xs[r*256 + c4] = *(const float4*)&x[(size_t)(rowbase+r)*DD + c4];
    }
    for (int i = tid; i < 2048; i += NTHR){
        *(float4*)&wk[i*4] = *(const float4*)&Wk[i*4];
    }
    __syncthreads();
    int w = tid >> 5, p = tid & 31;
    int t0 = 2*w;
    float bkp = bk[p];
    float s0 = bkp, s1 = bkp;
    #pragma unroll 16
    for (int k = 0; k < 256; k++){
        float wv = wk[k*32 + p];
        s0 += xs[t0*256 + k]*wv;
        s1 += xs[(t0+1)*256 + k]*wv;
    }
    const float PI = 3.14159265358979323846f;
    float sn, cs;
    sincosf(tanhf(s0)*PI, &sn, &cs); d_cq[(rowbase+t0  )*PP+p]=cs; d_sq[(rowbase+t0  )*PP+p]=sn;
    sincosf(tanhf(s1)*PI, &sn, &cs); d_cq[(rowbase+t0+1)*PP+p]=cs; d_sq[(rowbase+t0+1)*PP+p]=sn;
}

// ---------------- gate finalize + scan ----------------
__device__ void cumsum_job(int b, const float* __restrict__ bg2, float* smem){
    int tid = threadIdx.x;
    int lane = tid & 31, warp = tid >> 5;
    float* wtot = smem;
    float bv = bg2[0];
    float v[4]; float run = 0.f;
    #pragma unroll
    for (int i=0;i<4;i++){
        int tok = b*LL + tid*4 + i;
        float4 a = *(const float4*)&d_gpart[(size_t)tok*8];
        float4 c = *(const float4*)&d_gpart[(size_t)tok*8 + 4];
        float s = bv + a.x+a.y+a.z+a.w + c.x+c.y+c.z+c.w;
        float g = 1.f/(1.f + expf(-s));
        d_g[tok] = g;
        run += g; v[i] = run;
    }
    float x = run;
    #pragma unroll
    for (int o=1;o<32;o<<=1){
        float y = __shfl_up_sync(0xffffffffu, x, o);
        if (lane >= o) x += y;
    }
    if (lane == 31) wtot[warp] = x;
    __syncthreads();
    if (warp == 0 && lane < 16){
        float t = wtot[lane];
        #pragma unroll
        for (int o=1;o<16;o<<=1){
            float z = __shfl_up_sync(0xffffu, t, o);
            if (lane >= o) t += z;
        }
        wtot[lane] = t;
    }
    __syncthreads();
    float off = (x - run) + (warp ? wtot[warp-1] : 0.f);
    float* gc = d_gc + b*LL + tid*4;
    #pragma unroll
    for (int i=0;i<4;i++) gc[i] = v[i] + off;
}

// ---------------- chunk state slice ----------------
__device__ void chunk_state_job(int cc, int b, int tile, const float* __restrict__ bg2,
                                float* smem){
    float* sA = smem;
    float* sB = sA + 64*36;
    float* sg = sB + 32*264;
    const int tid = threadIdx.x;
    const int wid = tid >> 5, lane = tid & 31;
    const int grp = lane >> 2, tig = lane & 3;
    const int wm = wid >> 3;
    const int wn = wid & 7;

    int t0 = cc*CH + tile*32;
    if (tid < 32){
        int tok = b*LL + t0 + tid;
        float4 a = *(const float4*)&d_gpart[(size_t)tok*8];
        float4 c = *(const float4*)&d_gpart[(size_t)tok*8 + 4];
        float s = bg2[0] + a.x+a.y+a.z+a.w + c.x+c.y+c.z+c.w;
        sg[tid] = 1.f/(1.f + expf(-s));
    }

    float acc[2][4][4];
    #pragma unroll
    for (int mt=0;mt<2;mt++)
        #pragma unroll
        for (int nt=0;nt<4;nt++)
            #pragma unroll
            for (int i=0;i<4;i++) acc[mt][nt][i]=0.f;

    for (int i = tid; i < 64*32; i += NTHR){
        int p = i>>5, t = i&31;
        int gt = t0 + t;
        sA[p*36 + t] = (gt >= 1) ? f2tf_as_f(phasor(b, gt-1, p)) : 0.f;
    }
    __syncthreads();
    for (int i = tid; i < 32*64; i += NTHR){
        int t = i>>6, c4 = (i&63)*4;
        float gv = sg[t];
        float4 v = *(const float4*)&d_v[((size_t)(b*LL + t0 + t))*DD + c4];
        v.x = f2tf_as_f(v.x*gv); v.y = f2tf_as_f(v.y*gv);
        v.z = f2tf_as_f(v.z*gv); v.w = f2tf_as_f(v.w*gv);
        *(float4*)&sB[t*264 + c4] = v;
    }
    __syncthreads();
    const uint32_t abase = shaddr(sA) + ldsm_off(lane, wm*32, 36);
    #pragma unroll
    for (int ks = 0; ks < 32; ks += 8){
        uint32_t afr[2][4], bfr[4][2];
        #pragma unroll
        for (int mt=0; mt<2; mt++)
            ldsm4(afr[mt], abase + (mt*16*36 + ks)*4);
        #pragma unroll
        for (int nt=0; nt<4; nt++){
            int cb = wn*32 + nt*8 + grp;
            bfr[nt][0] = fb(sB[(ks + tig    )*264 + cb]);
            bfr[nt][1] = fb(sB[(ks + tig + 4)*264 + cb]);
        }
        #pragma unroll
        for (int mt=0; mt<2; mt++)
            #pragma unroll
            for (int nt=0; nt<4; nt++)
                mma_tf32(acc[mt][nt], afr[mt], bfr[nt]);
    }
    __syncthreads();
    size_t base = ((size_t)(b*64 + cc*4 + tile))*64*DD;
    #pragma unroll
    for (int mt=0; mt<2; mt++)
        #pragma unroll
        for (int nt=0; nt<4; nt++)
            #pragma unroll
            for (int half=0; half<2; half++){
                int row = wm*32 + mt*16 + grp + half*8;
                int col = wn*32 + nt*8 + 2*tig;
                *(float2*)&d_state[base + (size_t)row*DD + col] =
                    make_float2(acc[mt][nt][half*2], acc[mt][nt][half*2+1]);
            }
}

// ---------------- chunk prefix over 64 slices ----------------
__device__ void chunk_prefix_job(int b, int gs){
    int off = gs*2048 + threadIdx.x*4;
    float4 run = make_float4(0.f,0.f,0.f,0.f);
    #pragma unroll 8
    for (int c = 0; c < 64; c++){
        size_t base = ((size_t)(b*64 + c))*16384 + off;
        float4 v = *(const float4*)&d_state[base];
        if ((c & 3) == 0){
            size_t pb = ((size_t)(b*NCH + (c>>2)))*16384 + off;
            *(float4*)&d_pref[pb] = run;
        }
        run.x += v.x; run.y += v.y; run.z += v.z; run.w += v.w;
    }
}

// ---------------- chunk out part 1: load tiles + masked scores ----------------
__device__ void chunk_out_scores(int cc, int ds, int b, float* sm){
    float* sQ  = sm;
    float* sKT = sQ + 128*68;
    float* sS  = sKT + 64*136;
    float* sV  = sS + 128*132;
    const int tid = threadIdx.x;
    const int wid = tid >> 5, lane = tid & 31;
    const int grp = lane >> 2, tig = lane & 3;

    for (int i = tid; i < CH*64; i += NTHR){
        int r = i>>6, c = i&63;
        sQ[r*68 + c] = f2tf_as_f(phasor(b, cc*CH + r, c));
    }
    for (int i = tid; i < CH*64; i += NTHR){
        int t = i>>6, c = i&63;
        int gt = cc*CH + t;
        sKT[c*136 + t] = (gt >= 1) ? f2tf_as_f(phasor(b, gt-1, c)) : 0.f;
    }
    for (int i = tid; i < 128*16; i += NTHR){
        int t = i>>4, c4 = (i&15)*4;
        float gv = d_g[b*LL + cc*CH + t];
        float4 v = *(const float4*)&d_v[((size_t)(b*LL + cc*CH + t))*DD + ds*64 + c4];
        v.x = f2tf_as_f(v.x*gv); v.y = f2tf_as_f(v.y*gv);
        v.z = f2tf_as_f(v.z*gv); v.w = f2tf_as_f(v.w*gv);
        *(float4*)&sV[t*72 + c4] = v;
    }
    __syncthreads();

    const int wm = wid >> 2;
    const int wn = wid & 3;
    if (wn > wm){
        #pragma unroll
        for (int mt=0; mt<2; mt++)
            #pragma unroll
            for (int nt=0; nt<4; nt++)
                #pragma unroll
                for (int half=0; half<2; half++){
                    int row = wm*32 + mt*16 + grp + half*8;
                    int col = wn*32 + nt*8 + 2*tig;
                    *(float2*)&sS[row*132 + col] = make_float2(0.f, 0.f);
                }
        return;
    }
    float acc2[2][4][4];
    #pragma unroll
    for (int mt=0;mt<2;mt++)
        #pragma unroll
        for (int nt=0;nt<4;nt++)
            #pragma unroll
            for (int i=0;i<4;i++) acc2[mt][nt][i]=0.f;
    const uint32_t qbase = shaddr(sQ) + ldsm_off(lane, wm*32, 68);
    #pragma unroll
    for (int ks = 0; ks < 64; ks += 8){
        uint32_t afr[2][4], bfr[4][2];
        #pragma unroll
        for (int mt=0; mt<2; mt++)
            ldsm4(afr[mt], qbase + (mt*16*68 + ks)*4);
        #pragma unroll
        for (int nt=0; nt<4; nt++){
            int cb = wn*32 + nt*8 + grp;
            bfr[nt][0] = fb(sKT[(ks + tig    )*136 + cb]);
            bfr[nt][1] = fb(sKT[(ks + tig + 4)*136 + cb]);
        }
        #pragma unroll
        for (int mt=0; mt<2; mt++)
            #pragma unroll
            for (int nt=0; nt<4; nt++)
                mma_tf32(acc2[mt][nt], afr[mt], bfr[nt]);
    }
    #pragma unroll
    for (int mt=0; mt<2; mt++)
        #pragma unroll
        for (int nt=0; nt<4; nt++)
            #pragma unroll
            for (int half=0; half<2; half++){
                int row = wm*32 + mt*16 + grp + half*8;
                int col = wn*32 + nt*8 + 2*tig;
                sS[row*132 + col    ] = (col   <= row) ? acc2[mt][nt][half*2  ] : 0.f;
                sS[row*132 + col + 1] = (col+1 <= row) ? acc2[mt][nt][half*2+1] : 0.f;
            }
}

// ---------------- chunk out part 2: load prefix + causal-bounded S@V + Q@P ----------------
__device__ void chunk_out_av(int cc, int ds, int b, float* sm){
    float* sQ  = sm;
    float* sKT = sQ + 128*68;
    float* sS  = sKT + 64*136;
    float* sV  = sS + 128*132;
    float* sP  = sV + 128*72;
    const int tid = threadIdx.x;
    const int wid = tid >> 5, lane = tid & 31;
    const int grp = lane >> 2, tig = lane & 3;

    size_t pbase = ((size_t)(b*NCH + cc))*64*DD;
    for (int i = tid; i < 64*16; i += NTHR){
        int p = i>>4, c4 = (i&15)*4;
        float4 v = *(const float4*)&d_pref[pbase + (size_t)p*DD + ds*64 + c4];
        v.x = f2tf_as_f(v.x); v.y = f2tf_as_f(v.y);
        v.z = f2tf_as_f(v.z); v.w = f2tf_as_f(v.w);
        *(float4*)&sP[p*72 + c4] = v;
    }
    __syncthreads();

    const int wm = wid >> 1;
    const int wn = wid & 1;
    float acc[4][4];
    #pragma unroll
    for (int nt=0;nt<4;nt++)
        #pragma unroll
        for (int i=0;i<4;i++) acc[nt][i]=0.f;

    const uint32_t sbase = shaddr(sS) + ldsm_off(lane, wm*16, 132);
    const int kmax = (wm+1)*16;
    #pragma unroll 2
    for (int ks = 0; ks < kmax; ks += 8){
        uint32_t afr[4], bfr[4][2];
        ldsm4(afr, sbase + ks*4);
        #pragma unroll
        for (int nt=0; nt<4; nt++){
            int cb = wn*32 + nt*8 + grp;
            bfr[nt][0] = fb(sV[(ks + tig    )*72 + cb]);
            bfr[nt][1] = fb(sV[(ks + tig + 4)*72 + cb]);
        }
        #pragma unroll
        for (int nt=0; nt<4; nt++)
            mma_tf32(acc[nt], afr, bfr[nt]);
    }
    const uint32_t qb2 = shaddr(sQ) + ldsm_off(lane, wm*16, 68);
    #pragma unroll
    for (int ks = 0; ks < 64; ks += 8){
        uint32_t afr[4], bfr[4][2];
        ldsm4(afr, qb2 + ks*4);
        #pragma unroll
        for (int nt=0; nt<4; nt++){
            int cb = wn*32 + nt*8 + grp;
            bfr[nt][0] = fb(sP[(ks + tig    )*72 + cb]);
            bfr[nt][1] = fb(sP[(ks + tig + 4)*72 + cb]);
        }
        #pragma unroll
        for (int nt=0; nt<4; nt++)
            mma_tf32(acc[nt], afr, bfr[nt]);
    }

    int slot = ds*2 + wn;
    #pragma unroll
    for (int half=0; half<2; half++){
        int rloc = wm*16 + grp + half*8;
        int gtok = b*LL + cc*CH + rloc;
        float sc = rsqrtf(fmaxf(d_gc[gtok], 1.f)) * 0.17677669529663687f;
        float s = 0.f, ss = 0.f;
        #pragma unroll
        for (int nt=0; nt<4; nt++){
            int col = wn*32 + nt*8 + 2*tig;
            float v0 = acc[nt][half*2+0]*sc;
            float v1 = acc[nt][half*2+1]*sc;
            *(float2*)&d_ret[(size_t)gtok*DD + ds*64 + col] = make_float2(v0, v1);
            s += v0 + v1; ss += v0*v0 + v1*v1;
        }
        s  += __shfl_xor_sync(0xffffffffu, s, 1);
        s  += __shfl_xor_sync(0xffffffffu, s, 2);
        ss += __shfl_xor_sync(0xffffffffu, ss, 1);
        ss += __shfl_xor_sync(0xffffffffu, ss, 2);
        if (tig == 0){
            d_s1[slot*NTOK + gtok] = s;
            d_s2[slot*NTOK + gtok] = ss;
        }
    }
}

// ---------------- mega kernel ----------------
#define MEGA_SMEM ((128*68 + 64*136 + 128*132 + 128*72 + 64*72)*(int)sizeof(float))

__global__ void __launch_bounds__(NTHR, 1)
mega_kernel(const float* __restrict__ x,
            const float* __restrict__ Wk,  const float* __restrict__ bk,
            const float* __restrict__ Wv,  const float* __restrict__ bv,
            const float* __restrict__ Wg1, const float* __restrict__ bg1,
            const float* __restrict__ Wg2, const float* __restrict__ bg2,
            const float* __restrict__ ln1g,const float* __restrict__ ln1b,
            const float* __restrict__ Wr1, const float* __restrict__ br1,
            const float* __restrict__ Wr2, const float* __restrict__ br2,
            const float* __restrict__ ln2g,const float* __restrict__ ln2b,
            const float* __restrict__ Wo,  const float* __restrict__ bo,
            float* __restrict__ out)
{
    extern __shared__ __align__(16) float smem[];
    __shared__ unsigned s_bar[2];
    const int blk = blockIdx.x;
    const int m0 = (blk & 31)*128;
    const int n0 = (blk >> 5)*64;

    if (threadIdx.x == 0){ s_bar[0] = d_gen; s_bar[1] = 0; }
    // (ordering covered by the __syncthreads inside the first gbar / gemm loop)

    // Phase A: fused gate + value GEMM, then phases
    gemm_tile_a(smem, x, Wg1, bg1, Wg2, d_gpart, Wv, bv, d_v, m0, n0);
    phases_job(blk, x, Wk, bk, smem);
    gbar(s_bar);

    // Phase B||C: blocks 0-1 run the scan; all blocks compute states with local g
    if (blk < BB) cumsum_job(blk, bg2, smem);
    __syncthreads();
    chunk_state_job((blk >> 2) & 15, blk >> 6, blk & 3, bg2, smem);
    gbar(s_bar);

    // Phase D||E part 1: blocks 0-15 do the prefix; all blocks load tiles + scores
    if (blk < 16) chunk_prefix_job(blk >> 3, blk & 7);
    chunk_out_scores((blk >> 2) & 15, blk & 3, blk >> 6, smem);
    gbar(s_bar);

    // Phase E part 2: prefix load + causal-bounded AV
    chunk_out_av((blk >> 2) & 15, blk & 3, blk >> 6, smem);
    gbar(s_bar);

    // Phase F: dual-N fused
    gemm_tile_f(smem, d_ret, Wr1, br1, d_t1,
        d_s1, d_s2, ln1g, ln1b, m0, n0);
    gbar(s_bar);

    // Phase G
    gemm_tile<A_PLAIN, E_STAT>(smem, d_t1, Wr2, br2, d_t2, nullptr,
        nullptr, nullptr, nullptr, nullptr, d_s1b, d_s2b,
        m0, n0, NTOK, DD, 2*DD);
    gbar(s_bar);

    // Phase H
    gemm_tile<A_LN, E_OUT>(smem, d_t2, Wo, bo, out, x,
        d_s1b, d_s2b, ln2g, ln2b, nullptr, nullptr,
        m0, n0, NTOK, DD, DD);
}

// ---------------- launch ----------------
extern "C" void kernel_launch(void* const* d_in, const int* in_sizes, int n_in,
                              void* d_out, int out_size)
{
    const float* x    = (const float*)d_in[0];
    const float* Wk   = (const float*)d_in[1];
    const float* bk   = (const float*)d_in[2];
    const float* Wv   = (const float*)d_in[3];
    const float* bv   = (const float*)d_in[4];
    const float* Wg1  = (const float*)d_in[5];
    const float* bg1  = (const float*)d_in[6];
    const float* Wg2  = (const float*)d_in[7];
    const float* bg2  = (const float*)d_in[8];
    const float* ln1g = (const float*)d_in[9];
    const float* ln1b = (const float*)d_in[10];
    const float* Wr1  = (const float*)d_in[11];
    const float* br1  = (const float*)d_in[12];
    const float* Wr2  = (const float*)d_in[13];
    const float* br2  = (const float*)d_in[14];
    const float* ln2g = (const float*)d_in[15];
    const float* ln2b = (const float*)d_in[16];
    const float* Wo   = (const float*)d_in[17];
    const float* bo   = (const float*)d_in[18];
    float* out = (float*)d_out;

    static bool init = false;
    if (!init){
        cudaFuncSetAttribute(mega_kernel, cudaFuncAttributeMaxDynamicSharedMemorySize, MEGA_SMEM);
        init = true;
    }

    mega_kernel<<<NBLK, NTHR, MEGA_SMEM>>>(
        x, Wk, bk, Wv, bv, Wg1, bg1, Wg2, bg2,
        ln1g, ln1b, Wr1, br1, Wr2, br2, ln2g, ln2b, Wo, bo, out);
    (void)in_sizes; (void)n_in; (void)out_size;
}